// round 5
// baseline (speedup 1.0000x reference)
#include <cuda_runtime.h>
#include <cuda_bf16.h>
#include <cstdint>

// ---------------------------------------------------------------------------
// S6 block, legacy mma.sync path (tcgen05 unavailable on this build: harness
// PTX targets compute_103 without the 'a' suffix).
// gemm1 (128x256 CTA, 64x64 warp tiles, fused elementwise epilogue, permuted
// W cols) -> chunked scan -> gemm2. 3-term bf16 split, dedup hi segments.
// Shapes fixed: B=4, L=4096, Cin=256, N=512, Cout=256.
// ---------------------------------------------------------------------------

constexpr int kBL = 16384, kN = 512, kCout = 256, kL = 4096, kB = 4;
constexpr int kNCH = 32, kCH = 128;

// ------------------------- scratch (device globals) ------------------------
__device__ __nv_bfloat16 g_xp [(size_t)kBL * 512];    // [row][ xh(256) | xl(256) ]
__device__ __nv_bfloat16 g_Wp1[(size_t)512 * 2048];   // [ wh(256)|wl(256) ][ jperm ]
__device__ __nv_bfloat16 g_y1p[(size_t)kBL * 1024];   // [row][ yh(512) | yl(512) ]
__device__ __nv_bfloat16 g_Wyp[(size_t)1024 * 256];   // [ wh(512)|wl(512) ][ j ]
__device__ float g_a[(size_t)kBL * kN];
__device__ float g_u[(size_t)kBL * kN];
__device__ float g_c[(size_t)kBL * kN];
__device__ float g_Ag[kB * kNCH * kN];
__device__ float g_Bg[kB * kNCH * kN];
__device__ float g_H [kB * kNCH * kN];

__device__ __forceinline__ uint32_t smem_u32(const void* p) {
    return (uint32_t)__cvta_generic_to_shared(p);
}

// ------------------------------ pack kernels --------------------------------
__global__ void pack_x_kernel(const float* __restrict__ x) {
    int idx = blockIdx.x * 256 + threadIdx.x;            // kBL*64 total
    int row = idx >> 6, k4 = (idx & 63) << 2;
    float4 v = *(const float4*)(x + (size_t)row * 256 + k4);
    __nv_bfloat16 h0 = __float2bfloat16(v.x), h1 = __float2bfloat16(v.y);
    __nv_bfloat16 h2 = __float2bfloat16(v.z), h3 = __float2bfloat16(v.w);
    __nv_bfloat16 l0 = __float2bfloat16(v.x - __bfloat162float(h0));
    __nv_bfloat16 l1 = __float2bfloat16(v.y - __bfloat162float(h1));
    __nv_bfloat16 l2 = __float2bfloat16(v.z - __bfloat162float(h2));
    __nv_bfloat16 l3 = __float2bfloat16(v.w - __bfloat162float(h3));
    __nv_bfloat162* ph = (__nv_bfloat162*)(g_xp + (size_t)row * 512 + k4);
    ph[0] = __halves2bfloat162(h0, h1);
    ph[1] = __halves2bfloat162(h2, h3);
    __nv_bfloat162* pl = (__nv_bfloat162*)(g_xp + (size_t)row * 512 + 256 + k4);
    pl[0] = __halves2bfloat162(l0, l1);
    pl[1] = __halves2bfloat162(l2, l3);
}

// Permuted W1 columns. For j = n128*128 + w*32 + nf*8 + q2*2 + r:
//   group g = n128*32 + w*8 + (nf>>1)*4 + q2,  member m = (nf&1)*2 + r
//   m: 0=Wx[:,g] 1=Wbc[:,g] 2=Wbc[:,512+g] 3=Wd[:,g]
__global__ void pack_w1_kernel(const float* __restrict__ Wx,
                               const float* __restrict__ Wbc,
                               const float* __restrict__ Wd) {
    int idx = blockIdx.x * 256 + threadIdx.x;            // 512*2048 total
    int kk = idx >> 11, j = idx & 2047;
    int seg = kk >> 8, k = kk & 255;
    int g = (j >> 7) * 32 + ((j >> 5) & 3) * 8 + ((j >> 4) & 1) * 4 + ((j >> 1) & 3);
    int m = ((j >> 3) & 1) * 2 + (j & 1);
    float w;
    if (m == 0)      w = Wx [k * 512  + g];
    else if (m == 1) w = Wbc[k * 1024 + g];
    else if (m == 2) w = Wbc[k * 1024 + 512 + g];
    else             w = Wd [k * 512  + g];
    __nv_bfloat16 hi = __float2bfloat16(w);
    __nv_bfloat16 o  = hi;
    if (seg == 1) o = __float2bfloat16(w - __bfloat162float(hi));
    g_Wp1[(size_t)kk * 2048 + j] = o;
}

__global__ void pack_wy_kernel(const float* __restrict__ Wy) {
    int idx = blockIdx.x * 256 + threadIdx.x;            // 1024*256 total
    int kk = idx >> 8, j = idx & 255;
    int seg = kk >> 9, k = kk & 511;
    float w = Wy[k * 256 + j];
    __nv_bfloat16 hi = __float2bfloat16(w);
    __nv_bfloat16 o  = hi;
    if (seg == 1) o = __float2bfloat16(w - __bfloat162float(hi));
    g_Wyp[(size_t)kk * 256 + j] = o;
}

// ------------------------------ GEMM (mma.sync) -----------------------------
// CTA 128x256, 8 warps in 2x4, warp tile 64x64, k-tile 32, 4-stage cp.async.
#define STAGES 4
constexpr int AROW = 40;                       // A smem row elems (32 + pad 8)
constexpr int BROW = 264;                      // B smem row elems (256 + pad 8)
constexpr int A_ST = 128 * AROW;               // 5120 elems / stage
constexpr int B_ST = 32 * BROW;                // 8448 elems / stage
constexpr int SM_B = STAGES * A_ST;
constexpr int GEMM_SMEM = (STAGES * (A_ST + B_ST)) * 2;   // 108544 bytes

// MODE 1: A=g_xp(512), B=g_Wp1(2048), KBASE=256, fused S6 epilogue.
// MODE 2: A=g_y1p(1024), B=g_Wyp(256), KBASE=512, bias epilogue -> out.
template <int MODE>
__global__ void __launch_bounds__(256, 1)
gemm_fused(const __nv_bfloat16* __restrict__ A,
           const __nv_bfloat16* __restrict__ Bw,
           const float* __restrict__ bias,
           const float* __restrict__ bx, const float* __restrict__ bbc,
           const float* __restrict__ bd,
           float* __restrict__ Cout_) {
    extern __shared__ __align__(16) __nv_bfloat16 sm[];
    __nv_bfloat16* As = sm;
    __nv_bfloat16* Bs = sm + SM_B;

    constexpr int KBASE = (MODE == 1) ? 256 : 512;
    constexpr int S  = KBASE / 32;
    constexpr int KT = 3 * S;
    constexpr int strideA = 2 * KBASE;
    constexpr int NB = (MODE == 1) ? 2048 : 256;

    const int tid = threadIdx.x, lane = tid & 31, warp = tid >> 5;
    const int wm = (warp >> 2) * 64, wn = (warp & 3) * 64;
    const int bm = blockIdx.y * 128, bn = blockIdx.x * 256;

    float acc[4][8][4];
#pragma unroll
    for (int i = 0; i < 4; i++)
#pragma unroll
        for (int j = 0; j < 8; j++)
#pragma unroll
            for (int q = 0; q < 4; q++) acc[i][j][q] = 0.f;

    auto load_tile = [&](int kt, int st) {
        int seg = (kt >= 2 * S) ? 2 : ((kt >= S) ? 1 : 0);
        int kk  = kt - seg * S;
        int aoff = ((seg == 2) ? KBASE : 0) + kk * 32;
        int boff = ((seg == 1) ? KBASE : 0) + kk * 32;
        const __nv_bfloat16* Ab = A + (size_t)bm * strideA + aoff;
        __nv_bfloat16* as = As + st * A_ST;
#pragma unroll
        for (int i = 0; i < 2; i++) {                // 128 rows x 4 chunks
            int c = tid + i * 256;
            int row = c >> 2, sg = c & 3;
            asm volatile("cp.async.cg.shared.global [%0], [%1], 16;" ::
                         "r"(smem_u32(as + row * AROW + sg * 8)),
                         "l"(Ab + (size_t)row * strideA + sg * 8));
        }
        const __nv_bfloat16* Bb = Bw + (size_t)boff * NB + bn;
        __nv_bfloat16* bs = Bs + st * B_ST;
#pragma unroll
        for (int i = 0; i < 4; i++) {                // 32 rows x 32 chunks
            int c = tid + i * 256;
            int row = c >> 5, sg = c & 31;
            asm volatile("cp.async.cg.shared.global [%0], [%1], 16;" ::
                         "r"(smem_u32(bs + row * BROW + sg * 8)),
                         "l"(Bb + (size_t)row * NB + sg * 8));
        }
        asm volatile("cp.async.commit_group;");
    };

    load_tile(0, 0);
    load_tile(1, 1);
    load_tile(2, 2);

#pragma unroll 1
    for (int kt = 0; kt < KT; kt++) {
        int s = kt & 3;
        if (kt + 2 < KT)      asm volatile("cp.async.wait_group 2;");
        else if (kt + 1 < KT) asm volatile("cp.async.wait_group 1;");
        else                  asm volatile("cp.async.wait_group 0;");
        __syncthreads();
        if (kt + 3 < KT) load_tile(kt + 3, (kt + 3) & 3);

        __nv_bfloat16* as = As + s * A_ST;
        __nv_bfloat16* bs = Bs + s * B_ST;
#pragma unroll
        for (int ks = 0; ks < 2; ks++) {
            uint32_t af[4][4];
            uint32_t bf[8][2];
#pragma unroll
            for (int mf = 0; mf < 4; mf++) {
                uint32_t addr = smem_u32(
                    as + (wm + mf * 16 + (lane & 15)) * AROW + ks * 16 + (lane >> 4) * 8);
                asm volatile(
                    "ldmatrix.sync.aligned.m8n8.x4.shared.b16 {%0,%1,%2,%3}, [%4];\n"
                    : "=r"(af[mf][0]), "=r"(af[mf][1]), "=r"(af[mf][2]), "=r"(af[mf][3])
                    : "r"(addr));
            }
#pragma unroll
            for (int p = 0; p < 4; p++) {
                uint32_t addr = smem_u32(
                    bs + (ks * 16 + (lane & 15)) * BROW + wn + p * 16 + (lane >> 4) * 8);
                uint32_t r0, r1, r2, r3;
                asm volatile(
                    "ldmatrix.sync.aligned.m8n8.x4.trans.shared.b16 {%0,%1,%2,%3}, [%4];\n"
                    : "=r"(r0), "=r"(r1), "=r"(r2), "=r"(r3)
                    : "r"(addr));
                bf[p * 2][0] = r0;     bf[p * 2][1] = r1;
                bf[p * 2 + 1][0] = r2; bf[p * 2 + 1][1] = r3;
            }
#pragma unroll
            for (int mf = 0; mf < 4; mf++) {
#pragma unroll
                for (int nf = 0; nf < 8; nf++) {
                    asm volatile(
                        "mma.sync.aligned.m16n8k16.row.col.f32.bf16.bf16.f32 "
                        "{%0,%1,%2,%3}, {%4,%5,%6,%7}, {%8,%9}, {%0,%1,%2,%3};\n"
                        : "+f"(acc[mf][nf][0]), "+f"(acc[mf][nf][1]),
                          "+f"(acc[mf][nf][2]), "+f"(acc[mf][nf][3])
                        : "r"(af[mf][0]), "r"(af[mf][1]), "r"(af[mf][2]), "r"(af[mf][3]),
                          "r"(bf[nf][0]), "r"(bf[nf][1]));
                }
            }
        }
    }

    if (MODE == 2) {
#pragma unroll
        for (int mf = 0; mf < 4; mf++) {
#pragma unroll
            for (int nf = 0; nf < 8; nf++) {
                int row = bm + wm + mf * 16 + (lane >> 2);
                int col = bn + wn + nf * 8 + (lane & 3) * 2;
                float b0 = bias[col], b1 = bias[col + 1];
                *reinterpret_cast<float2*>(Cout_ + (size_t)row * kCout + col) =
                    make_float2(acc[mf][nf][0] + b0, acc[mf][nf][1] + b1);
                *reinterpret_cast<float2*>(Cout_ + (size_t)(row + 8) * kCout + col) =
                    make_float2(acc[mf][nf][2] + b0, acc[mf][nf][3] + b1);
            }
        }
    } else {
        // Fused S6 elementwise: warp tile covers two 32-col chunks (w, w+1).
        // nf-block t in {0,1}: nf = 4t+{0,1} -> group gbase+t*8, members 0..3;
        //                      nf = 4t+{2,3} -> group gbase+t*8+4.
        const int gbase = (bn >> 2) + (wn >> 2) + (lane & 3);
#pragma unroll
        for (int t = 0; t < 2; t++) {
            int g0 = gbase + t * 8;
            float vbx0 = bx[g0],        vbx1 = bx[g0 + 4];
            float vbb0 = bbc[g0],       vbb1 = bbc[g0 + 4];
            float vbc0 = bbc[512 + g0], vbc1 = bbc[512 + g0 + 4];
            float vbd0 = bd[g0],        vbd1 = bd[g0 + 4];
#pragma unroll
            for (int mf = 0; mf < 4; mf++) {
                int Rb = bm + wm + mf * 16 + (lane >> 2);
#pragma unroll
                for (int h = 0; h < 2; h++) {
                    int R = Rb + h * 8;
                    size_t o = (size_t)R * kN;
                    {
                        float xv = acc[mf][4 * t + 0][h * 2 + 0] + vbx0;
                        float bv = acc[mf][4 * t + 0][h * 2 + 1] + vbb0;
                        float cc = acc[mf][4 * t + 1][h * 2 + 0] + vbc0;
                        float dd = acc[mf][4 * t + 1][h * 2 + 1] + vbd0;
                        float Aa = 1.0f / (1.0f + expf(dd));
                        g_a[o + g0] = Aa;
                        g_u[o + g0] = (1.0f - Aa) * bv * xv;
                        g_c[o + g0] = cc;
                    }
                    {
                        float xv = acc[mf][4 * t + 2][h * 2 + 0] + vbx1;
                        float bv = acc[mf][4 * t + 2][h * 2 + 1] + vbb1;
                        float cc = acc[mf][4 * t + 3][h * 2 + 0] + vbc1;
                        float dd = acc[mf][4 * t + 3][h * 2 + 1] + vbd1;
                        float Aa = 1.0f / (1.0f + expf(dd));
                        g_a[o + g0 + 4] = Aa;
                        g_u[o + g0 + 4] = (1.0f - Aa) * bv * xv;
                        g_c[o + g0 + 4] = cc;
                    }
                }
            }
        }
    }
}

// ------------------------------- chunked scan -------------------------------
__global__ void scan_phase1() {
    int n = threadIdx.x, ch = blockIdx.x, b = blockIdx.y;
    size_t base = ((size_t)(b * kL + ch * kCH)) * kN + n;
    float Ar = 1.f, Br = 0.f;
#pragma unroll 4
    for (int t = 0; t < kCH; t++) {
        size_t o = base + (size_t)t * kN;
        float a = g_a[o], u = g_u[o];
        Br = fmaf(a, Br, u);
        Ar *= a;
    }
    int idx = (b * kNCH + ch) * kN + n;
    g_Ag[idx] = Ar;
    g_Bg[idx] = Br;
}

__global__ void scan_phase2() {
    int n = threadIdx.x, b = blockIdx.x;
    float h = 0.f;
    for (int ch = 0; ch < kNCH; ch++) {
        int idx = (b * kNCH + ch) * kN + n;
        g_H[idx] = h;
        h = fmaf(g_Ag[idx], h, g_Bg[idx]);
    }
}

__global__ void scan_phase3() {
    int n = threadIdx.x, ch = blockIdx.x, b = blockIdx.y;
    int idx = (b * kNCH + ch) * kN + n;
    float h = g_H[idx];
    int row0 = b * kL + ch * kCH;
    size_t base = (size_t)row0 * kN + n;
#pragma unroll 4
    for (int t = 0; t < kCH; t++) {
        size_t o = base + (size_t)t * kN;
        float a = g_a[o], u = g_u[o], c = g_c[o];
        h = fmaf(a, h, u);
        float y = c * h;
        __nv_bfloat16 hi = __float2bfloat16(y);
        __nv_bfloat16 lo = __float2bfloat16(y - __bfloat162float(hi));
        size_t yo = (size_t)(row0 + t) * 1024 + n;
        g_y1p[yo]       = hi;
        g_y1p[yo + 512] = lo;
    }
}

// --------------------------------- launcher ---------------------------------
extern "C" void kernel_launch(void* const* d_in, const int* in_sizes, int n_in,
                              void* d_out, int out_size) {
    const float* x   = (const float*)d_in[0];
    const float* Wx  = (const float*)d_in[1];
    const float* bx  = (const float*)d_in[2];
    const float* Wbc = (const float*)d_in[3];
    const float* bbc = (const float*)d_in[4];
    const float* Wd  = (const float*)d_in[5];
    const float* bd  = (const float*)d_in[6];
    const float* Wy  = (const float*)d_in[7];
    const float* by  = (const float*)d_in[8];
    float* out = (float*)d_out;
    (void)in_sizes; (void)n_in; (void)out_size;

    void *p_xp, *p_wp1, *p_y1p, *p_wyp;
    cudaGetSymbolAddress(&p_xp,  g_xp);
    cudaGetSymbolAddress(&p_wp1, g_Wp1);
    cudaGetSymbolAddress(&p_y1p, g_y1p);
    cudaGetSymbolAddress(&p_wyp, g_Wyp);

    cudaFuncSetAttribute(gemm_fused<1>, cudaFuncAttributeMaxDynamicSharedMemorySize, GEMM_SMEM);
    cudaFuncSetAttribute(gemm_fused<2>, cudaFuncAttributeMaxDynamicSharedMemorySize, GEMM_SMEM);

    pack_x_kernel <<<(kBL * 64) / 256, 256>>>(x);
    pack_w1_kernel<<<(512 * 2048) / 256, 256>>>(Wx, Wbc, Wd);
    pack_wy_kernel<<<(1024 * 256) / 256, 256>>>(Wy);

    gemm_fused<1><<<dim3(8, 128), 256, GEMM_SMEM>>>(
        (const __nv_bfloat16*)p_xp, (const __nv_bfloat16*)p_wp1,
        nullptr, bx, bbc, bd, nullptr);

    scan_phase1<<<dim3(kNCH, kB), kN>>>();
    scan_phase2<<<kB, kN>>>();
    scan_phase3<<<dim3(kNCH, kB), kN>>>();

    gemm_fused<2><<<dim3(1, 128), 256, GEMM_SMEM>>>(
        (const __nv_bfloat16*)p_y1p, (const __nv_bfloat16*)p_wyp,
        by, nullptr, nullptr, nullptr, out);
}

// round 6
// speedup vs baseline: 1.1111x; 1.1111x over previous
#include <cuda_runtime.h>
#include <cuda_bf16.h>
#include <cstdint>

// ---------------------------------------------------------------------------
// S6 block, legacy mma.sync path (tcgen05 unavailable on this build).
// gemm1 (R4 config: 128x128 CTA, 64x32 warp tiles, fused elementwise epilogue
// + fused per-chunk scan aggregates) -> scan2 -> scan3 -> gemm2.
// 3-term bf16 error split with deduplicated hi segments.
// Shapes fixed: B=4, L=4096, Cin=256, N=512, Cout=256.
// ---------------------------------------------------------------------------

constexpr int kBL = 16384, kN = 512, kCout = 256, kL = 4096, kB = 4;
constexpr int kNCH = 32, kCH = 128;

// ------------------------- scratch (device globals) ------------------------
__device__ __nv_bfloat16 g_xp [(size_t)kBL * 512];    // [row][ xh(256) | xl(256) ]
__device__ __nv_bfloat16 g_Wp1[(size_t)512 * 2048];   // [ wh(256)|wl(256) ][ jperm ]
__device__ __nv_bfloat16 g_y1p[(size_t)kBL * 1024];   // [row][ yh(512) | yl(512) ]
__device__ __nv_bfloat16 g_Wyp[(size_t)1024 * 256];   // [ wh(512)|wl(512) ][ j ]
__device__ float g_a[(size_t)kBL * kN];
__device__ float g_u[(size_t)kBL * kN];
__device__ float g_c[(size_t)kBL * kN];
__device__ float g_Ag[kB * kNCH * kN];
__device__ float g_Bg[kB * kNCH * kN];
__device__ float g_H [kB * kNCH * kN];

__device__ __forceinline__ uint32_t smem_u32(const void* p) {
    return (uint32_t)__cvta_generic_to_shared(p);
}

// ------------------------------ pack kernels --------------------------------
__global__ void pack_x_kernel(const float* __restrict__ x) {
    int idx = blockIdx.x * 256 + threadIdx.x;            // kBL*64 total
    int row = idx >> 6, k4 = (idx & 63) << 2;
    float4 v = *(const float4*)(x + (size_t)row * 256 + k4);
    __nv_bfloat16 h0 = __float2bfloat16(v.x), h1 = __float2bfloat16(v.y);
    __nv_bfloat16 h2 = __float2bfloat16(v.z), h3 = __float2bfloat16(v.w);
    __nv_bfloat16 l0 = __float2bfloat16(v.x - __bfloat162float(h0));
    __nv_bfloat16 l1 = __float2bfloat16(v.y - __bfloat162float(h1));
    __nv_bfloat16 l2 = __float2bfloat16(v.z - __bfloat162float(h2));
    __nv_bfloat16 l3 = __float2bfloat16(v.w - __bfloat162float(h3));
    __nv_bfloat162* ph = (__nv_bfloat162*)(g_xp + (size_t)row * 512 + k4);
    ph[0] = __halves2bfloat162(h0, h1);
    ph[1] = __halves2bfloat162(h2, h3);
    __nv_bfloat162* pl = (__nv_bfloat162*)(g_xp + (size_t)row * 512 + 256 + k4);
    pl[0] = __halves2bfloat162(l0, l1);
    pl[1] = __halves2bfloat162(l2, l3);
}

// Permuted W1 columns. For j = n128*128 + w*32 + nf*8 + q2*2 + r:
//   group g = n128*32 + w*8 + (nf>>1)*4 + q2,  member m = (nf&1)*2 + r
//   m: 0=Wx[:,g] 1=Wbc[:,g] 2=Wbc[:,512+g] 3=Wd[:,g]
__global__ void pack_w1_kernel(const float* __restrict__ Wx,
                               const float* __restrict__ Wbc,
                               const float* __restrict__ Wd) {
    int idx = blockIdx.x * 256 + threadIdx.x;            // 512*2048 total
    int kk = idx >> 11, j = idx & 2047;
    int seg = kk >> 8, k = kk & 255;
    int g = (j >> 7) * 32 + ((j >> 5) & 3) * 8 + ((j >> 4) & 1) * 4 + ((j >> 1) & 3);
    int m = ((j >> 3) & 1) * 2 + (j & 1);
    float w;
    if (m == 0)      w = Wx [k * 512  + g];
    else if (m == 1) w = Wbc[k * 1024 + g];
    else if (m == 2) w = Wbc[k * 1024 + 512 + g];
    else             w = Wd [k * 512  + g];
    __nv_bfloat16 hi = __float2bfloat16(w);
    __nv_bfloat16 o  = hi;
    if (seg == 1) o = __float2bfloat16(w - __bfloat162float(hi));
    g_Wp1[(size_t)kk * 2048 + j] = o;
}

__global__ void pack_wy_kernel(const float* __restrict__ Wy) {
    int idx = blockIdx.x * 256 + threadIdx.x;            // 1024*256 total
    int kk = idx >> 8, j = idx & 255;
    int seg = kk >> 9, k = kk & 511;
    float w = Wy[k * 256 + j];
    __nv_bfloat16 hi = __float2bfloat16(w);
    __nv_bfloat16 o  = hi;
    if (seg == 1) o = __float2bfloat16(w - __bfloat162float(hi));
    g_Wyp[(size_t)kk * 256 + j] = o;
}

// ------------------------------ GEMM (mma.sync) -----------------------------
#define STAGES 4
constexpr int A_ST = 128 * 40;                 // elems per A stage (pad 8)
constexpr int B_ST = 32 * 136;                 // elems per B stage (pad 8)
constexpr int SM_B = STAGES * A_ST;
constexpr int SM_ELEMS = STAGES * (A_ST + B_ST);          // 37888 elems
constexpr int GEMM_SMEM = SM_ELEMS * 2 + 256;             // + reduce buffer

// MODE 1: A=g_xp(512), B=g_Wp1(2048), KBASE=256, fused S6 epilogue + chunk agg.
// MODE 2: A=g_y1p(1024), B=g_Wyp(256), KBASE=512, bias epilogue -> out.
template <int MODE>
__global__ void __launch_bounds__(256, 2)
gemm_fused(const __nv_bfloat16* __restrict__ A,
           const __nv_bfloat16* __restrict__ Bw,
           const float* __restrict__ bias,
           const float* __restrict__ bx, const float* __restrict__ bbc,
           const float* __restrict__ bd,
           float* __restrict__ Cout_) {
    extern __shared__ __align__(16) __nv_bfloat16 sm[];
    __nv_bfloat16* As = sm;
    __nv_bfloat16* Bs = sm + SM_B;

    constexpr int KBASE = (MODE == 1) ? 256 : 512;
    constexpr int S  = KBASE / 32;
    constexpr int KT = 3 * S;
    constexpr int strideA = 2 * KBASE;
    constexpr int NB = (MODE == 1) ? 2048 : 256;

    const int tid = threadIdx.x, lane = tid & 31, warp = tid >> 5;
    const int wm = (warp >> 2) * 64, wn = (warp & 3) * 32;
    const int bm = blockIdx.y * 128, bn = blockIdx.x * 128;

    float acc[4][4][4];
#pragma unroll
    for (int i = 0; i < 4; i++)
#pragma unroll
        for (int j = 0; j < 4; j++)
#pragma unroll
            for (int q = 0; q < 4; q++) acc[i][j][q] = 0.f;

    auto load_tile = [&](int kt, int st) {
        int seg = (kt >= 2 * S) ? 2 : ((kt >= S) ? 1 : 0);
        int kk  = kt - seg * S;
        int aoff = ((seg == 2) ? KBASE : 0) + kk * 32;
        int boff = ((seg == 1) ? KBASE : 0) + kk * 32;
        const __nv_bfloat16* Ab = A + (size_t)bm * strideA + aoff;
        __nv_bfloat16* as = As + st * A_ST;
#pragma unroll
        for (int i = 0; i < 2; i++) {
            int c = tid + i * 256;
            int row = c >> 2, sg = c & 3;
            asm volatile("cp.async.cg.shared.global [%0], [%1], 16;" ::
                         "r"(smem_u32(as + row * 40 + sg * 8)),
                         "l"(Ab + (size_t)row * strideA + sg * 8));
        }
        const __nv_bfloat16* Bb = Bw + (size_t)boff * NB + bn;
        __nv_bfloat16* bs = Bs + st * B_ST;
#pragma unroll
        for (int i = 0; i < 2; i++) {
            int c = tid + i * 256;
            int row = c >> 4, sg = c & 15;
            asm volatile("cp.async.cg.shared.global [%0], [%1], 16;" ::
                         "r"(smem_u32(bs + row * 136 + sg * 8)),
                         "l"(Bb + (size_t)row * NB + sg * 8));
        }
        asm volatile("cp.async.commit_group;");
    };

    load_tile(0, 0);
    load_tile(1, 1);
    load_tile(2, 2);

#pragma unroll 1
    for (int kt = 0; kt < KT; kt++) {
        int s = kt & 3;
        if (kt + 2 < KT)      asm volatile("cp.async.wait_group 2;");
        else if (kt + 1 < KT) asm volatile("cp.async.wait_group 1;");
        else                  asm volatile("cp.async.wait_group 0;");
        __syncthreads();
        if (kt + 3 < KT) load_tile(kt + 3, (kt + 3) & 3);

        __nv_bfloat16* as = As + s * A_ST;
        __nv_bfloat16* bs = Bs + s * B_ST;
#pragma unroll
        for (int ks = 0; ks < 2; ks++) {
            uint32_t af[4][4];
            uint32_t bf[4][2];
#pragma unroll
            for (int mf = 0; mf < 4; mf++) {
                uint32_t addr = smem_u32(
                    as + (wm + mf * 16 + (lane & 15)) * 40 + ks * 16 + (lane >> 4) * 8);
                asm volatile(
                    "ldmatrix.sync.aligned.m8n8.x4.shared.b16 {%0,%1,%2,%3}, [%4];\n"
                    : "=r"(af[mf][0]), "=r"(af[mf][1]), "=r"(af[mf][2]), "=r"(af[mf][3])
                    : "r"(addr));
            }
#pragma unroll
            for (int p = 0; p < 2; p++) {
                uint32_t addr = smem_u32(
                    bs + (ks * 16 + (lane & 15)) * 136 + wn + p * 16 + (lane >> 4) * 8);
                uint32_t r0, r1, r2, r3;
                asm volatile(
                    "ldmatrix.sync.aligned.m8n8.x4.trans.shared.b16 {%0,%1,%2,%3}, [%4];\n"
                    : "=r"(r0), "=r"(r1), "=r"(r2), "=r"(r3)
                    : "r"(addr));
                bf[p * 2][0] = r0;     bf[p * 2][1] = r1;
                bf[p * 2 + 1][0] = r2; bf[p * 2 + 1][1] = r3;
            }
#pragma unroll
            for (int mf = 0; mf < 4; mf++) {
#pragma unroll
                for (int nf = 0; nf < 4; nf++) {
                    asm volatile(
                        "mma.sync.aligned.m16n8k16.row.col.f32.bf16.bf16.f32 "
                        "{%0,%1,%2,%3}, {%4,%5,%6,%7}, {%8,%9}, {%0,%1,%2,%3};\n"
                        : "+f"(acc[mf][nf][0]), "+f"(acc[mf][nf][1]),
                          "+f"(acc[mf][nf][2]), "+f"(acc[mf][nf][3])
                        : "r"(af[mf][0]), "r"(af[mf][1]), "r"(af[mf][2]), "r"(af[mf][3]),
                          "r"(bf[nf][0]), "r"(bf[nf][1]));
                }
            }
        }
    }

    if (MODE == 2) {
#pragma unroll
        for (int mf = 0; mf < 4; mf++) {
#pragma unroll
            for (int nf = 0; nf < 4; nf++) {
                int row = bm + wm + mf * 16 + (lane >> 2);
                int col = bn + wn + nf * 8 + (lane & 3) * 2;
                float b0 = bias[col], b1 = bias[col + 1];
                *reinterpret_cast<float2*>(Cout_ + (size_t)row * kCout + col) =
                    make_float2(acc[mf][nf][0] + b0, acc[mf][nf][1] + b1);
                *reinterpret_cast<float2*>(Cout_ + (size_t)(row + 8) * kCout + col) =
                    make_float2(acc[mf][nf][2] + b0, acc[mf][nf][3] + b1);
            }
        }
    } else {
        // Fused S6 elementwise + per-chunk scan aggregates.
        // This CTA's 128 m-rows == one scan chunk (blockIdx.y = b*32+ch).
        // Thread's row (per mf,h): t_local(warp) = mf*16 + h*8 + q, q=lane>>2.
        // Order-aware butterfly over q bits, then sequential over (mf,h)
        // blocks, then lower/upper warp-row combine via smem.
        float2* buf2 = reinterpret_cast<float2*>(sm + SM_ELEMS);  // 32 float2
        const int gbase = (bn >> 2) + (wn >> 2) + (lane & 3);
        float Akeep[2], Bkeep[2];
#pragma unroll
        for (int t2 = 0; t2 < 2; t2++) {
            int g = gbase + t2 * 4;
            float vbx = bx[g], vbb = bbc[g], vbc = bbc[512 + g], vbd = bd[g];
            float At = 1.f, Bt = 0.f;
#pragma unroll
            for (int mf = 0; mf < 4; mf++) {
#pragma unroll
                for (int h = 0; h < 2; h++) {
                    int R = bm + wm + mf * 16 + h * 8 + (lane >> 2);
                    float xv = acc[mf][2 * t2 + 0][h * 2 + 0] + vbx;
                    float bv = acc[mf][2 * t2 + 0][h * 2 + 1] + vbb;
                    float cc = acc[mf][2 * t2 + 1][h * 2 + 0] + vbc;
                    float dd = acc[mf][2 * t2 + 1][h * 2 + 1] + vbd;
                    float Aa = 1.0f / (1.0f + expf(dd));
                    float uu = (1.0f - Aa) * bv * xv;
                    size_t o = (size_t)R * kN + g;
                    g_a[o] = Aa;
                    g_u[o] = uu;
                    g_c[o] = cc;
                    // butterfly over q (lane bits 2,3,4), ascending stride
                    float A1 = Aa, B1 = uu;
#pragma unroll
                    for (int st = 4; st <= 16; st <<= 1) {
                        float pa = __shfl_xor_sync(0xffffffffu, A1, st);
                        float pb = __shfl_xor_sync(0xffffffffu, B1, st);
                        if ((lane & st) == 0) {   // I'm earlier in t
                            B1 = pa * B1 + pb;
                            A1 = A1 * pa;
                        } else {                  // partner earlier
                            B1 = A1 * pb + B1;
                            A1 = pa * A1;
                        }
                    }
                    // sequential combine of 8-row block into warp-row total
                    Bt = A1 * Bt + B1;
                    At = At * A1;
                }
            }
            Akeep[t2] = At;
            Bkeep[t2] = Bt;
            if (warp < 4 && (lane >> 2) == 0) {   // rows 0-63 of chunk
                int lg = (warp & 3) * 8 + (lane & 3) + t2 * 4;
                buf2[lg] = make_float2(At, Bt);
            }
        }
        __syncthreads();
        if (warp >= 4 && (lane >> 2) == 0) {      // rows 64-127: finish combine
#pragma unroll
            for (int t2 = 0; t2 < 2; t2++) {
                int lg = (warp & 3) * 8 + (lane & 3) + t2 * 4;
                float2 lo = buf2[lg];
                int g = gbase + t2 * 4;
                float Ac = lo.x * Akeep[t2];
                float Bc = Akeep[t2] * lo.y + Bkeep[t2];
                int ci = blockIdx.y * kN + g;     // (b*32+ch)*512 + n
                g_Ag[ci] = Ac;
                g_Bg[ci] = Bc;
            }
        }
    }
}

// ------------------------------- chunked scan -------------------------------
__global__ void scan_phase2() {                   // exclusive prefix over chunks
    int n = threadIdx.x, b = blockIdx.x;
    float h = 0.f;
    for (int ch = 0; ch < kNCH; ch++) {
        int idx = (b * kNCH + ch) * kN + n;
        g_H[idx] = h;
        h = fmaf(g_Ag[idx], h, g_Bg[idx]);
    }
}

__global__ void scan_phase3() {                   // final scan, emit packed y1
    int n = threadIdx.x, ch = blockIdx.x, b = blockIdx.y;
    int idx = (b * kNCH + ch) * kN + n;
    float h = g_H[idx];
    int row0 = b * kL + ch * kCH;
    size_t base = (size_t)row0 * kN + n;
#pragma unroll 4
    for (int t = 0; t < kCH; t++) {
        size_t o = base + (size_t)t * kN;
        float a = g_a[o], u = g_u[o], c = g_c[o];
        h = fmaf(a, h, u);
        float y = c * h;
        __nv_bfloat16 hi = __float2bfloat16(y);
        __nv_bfloat16 lo = __float2bfloat16(y - __bfloat162float(hi));
        size_t yo = (size_t)(row0 + t) * 1024 + n;
        g_y1p[yo]       = hi;
        g_y1p[yo + 512] = lo;
    }
}

// --------------------------------- launcher ---------------------------------
extern "C" void kernel_launch(void* const* d_in, const int* in_sizes, int n_in,
                              void* d_out, int out_size) {
    const float* x   = (const float*)d_in[0];
    const float* Wx  = (const float*)d_in[1];
    const float* bx  = (const float*)d_in[2];
    const float* Wbc = (const float*)d_in[3];
    const float* bbc = (const float*)d_in[4];
    const float* Wd  = (const float*)d_in[5];
    const float* bd  = (const float*)d_in[6];
    const float* Wy  = (const float*)d_in[7];
    const float* by  = (const float*)d_in[8];
    float* out = (float*)d_out;
    (void)in_sizes; (void)n_in; (void)out_size;

    void *p_xp, *p_wp1, *p_y1p, *p_wyp;
    cudaGetSymbolAddress(&p_xp,  g_xp);
    cudaGetSymbolAddress(&p_wp1, g_Wp1);
    cudaGetSymbolAddress(&p_y1p, g_y1p);
    cudaGetSymbolAddress(&p_wyp, g_Wyp);

    cudaFuncSetAttribute(gemm_fused<1>, cudaFuncAttributeMaxDynamicSharedMemorySize, GEMM_SMEM);
    cudaFuncSetAttribute(gemm_fused<2>, cudaFuncAttributeMaxDynamicSharedMemorySize, GEMM_SMEM);

    pack_x_kernel <<<(kBL * 64) / 256, 256>>>(x);
    pack_w1_kernel<<<(512 * 2048) / 256, 256>>>(Wx, Wbc, Wd);
    pack_wy_kernel<<<(1024 * 256) / 256, 256>>>(Wy);

    gemm_fused<1><<<dim3(16, 128), 256, GEMM_SMEM>>>(
        (const __nv_bfloat16*)p_xp, (const __nv_bfloat16*)p_wp1,
        nullptr, bx, bbc, bd, nullptr);

    scan_phase2<<<kB, kN>>>();
    scan_phase3<<<dim3(kNCH, kB), kN>>>();

    gemm_fused<2><<<dim3(2, 128), 256, GEMM_SMEM>>>(
        (const __nv_bfloat16*)p_y1p, (const __nv_bfloat16*)p_wyp,
        by, nullptr, nullptr, nullptr, out);
}

// round 7
// speedup vs baseline: 1.1300x; 1.0170x over previous
#include <cuda_runtime.h>
#include <cuda_bf16.h>
#include <cuda_fp8.h>
#include <cstdint>

// ---------------------------------------------------------------------------
// S6 block, legacy mma.sync path (tcgen05 unavailable on this build).
// Split-precision GEMMs: main term bf16 (m16n8k16), correction terms e4m3
// fp8 (m16n8k32) folded into the same accumulator via a one-time 2^-14 scale.
// gemm1 keeps the fused S6 elementwise + per-chunk scan-aggregate epilogue.
// Shapes fixed: B=4, L=4096, Cin=256, N=512, Cout=256.
// ---------------------------------------------------------------------------

constexpr int kBL = 16384, kN = 512, kCout = 256, kL = 4096, kB = 4;
constexpr int kNCH = 32, kCH = 128;

// ------------------------- scratch (device globals) ------------------------
__device__ __nv_bfloat16 g_xp [(size_t)kBL * 256];   // xh, [row][256]
__device__ uint8_t       g_xp8[(size_t)kBL * 512];   // [row][ f8(x)(256) | f8(xl*2^10)(256) ]
__device__ __nv_bfloat16 g_Wp1[(size_t)256 * 2048];  // wh, [k][jperm]
__device__ uint8_t       g_Wp8[(size_t)256 * 4096];  // [q][j*2+b]: q<128 Wl*2^14 pairs, q>=128 Wh*2^4 pairs
__device__ __nv_bfloat16 g_y1p[(size_t)kBL * 512];   // yh, [row][512]
__device__ uint8_t       g_y8 [(size_t)kBL * 1024];  // [row][ f8(y)(512) | f8(yl*2^10)(512) ]
__device__ __nv_bfloat16 g_Wyp[(size_t)512 * 256];   // Wy hi, [k][j]
__device__ uint8_t       g_Wy8[(size_t)512 * 512];   // [q][j*2+b]: q<256 Wyl*2^14, q>=256 Wyh*2^4
__device__ float g_a[(size_t)kBL * kN];
__device__ float g_u[(size_t)kBL * kN];
__device__ float g_c[(size_t)kBL * kN];
__device__ float g_Ag[kB * kNCH * kN];
__device__ float g_Bg[kB * kNCH * kN];
__device__ float g_H [kB * kNCH * kN];

__device__ __forceinline__ uint32_t smem_u32(const void* p) {
    return (uint32_t)__cvta_generic_to_shared(p);
}
__device__ __forceinline__ uint8_t f8e4(float v) {
    return (uint8_t)__nv_cvt_float_to_fp8(v, __NV_SATFINITE, __NV_E4M3);
}

// ------------------------------ pack kernels --------------------------------
__global__ void pack_x_kernel(const float* __restrict__ x) {
    int idx = blockIdx.x * 256 + threadIdx.x;            // kBL*64 total
    int row = idx >> 6, k4 = (idx & 63) << 2;
    float4 v = *(const float4*)(x + (size_t)row * 256 + k4);
    float vv[4] = {v.x, v.y, v.z, v.w};
    __nv_bfloat16 hb[4];
    uint8_t hx[4], lx[4];
#pragma unroll
    for (int i = 0; i < 4; i++) {
        hb[i] = __float2bfloat16(vv[i]);
        float lo = vv[i] - __bfloat162float(hb[i]);
        hx[i] = f8e4(vv[i]);
        lx[i] = f8e4(lo * 1024.0f);
    }
    *(uint64_t*)(g_xp + (size_t)row * 256 + k4) = *(uint64_t*)hb;
    *(uint32_t*)(g_xp8 + (size_t)row * 512 + k4) = *(uint32_t*)hx;
    *(uint32_t*)(g_xp8 + (size_t)row * 512 + 256 + k4) = *(uint32_t*)lx;
}

// Permuted W1 columns. For j = n128*128 + w*32 + nf*8 + q2*2 + r:
//   group g = n128*32 + w*8 + (nf>>1)*4 + q2,  member m = (nf&1)*2 + r
//   m: 0=Wx[:,g] 1=Wbc[:,g] 2=Wbc[:,512+g] 3=Wd[:,g]
__global__ void pack_w1_kernel(const float* __restrict__ Wx,
                               const float* __restrict__ Wbc,
                               const float* __restrict__ Wd) {
    int idx = blockIdx.x * 256 + threadIdx.x;            // 256*2048 total
    int k = idx >> 11, j = idx & 2047;
    int g = (j >> 7) * 32 + ((j >> 5) & 3) * 8 + ((j >> 4) & 1) * 4 + ((j >> 1) & 3);
    int m = ((j >> 3) & 1) * 2 + (j & 1);
    float w;
    if (m == 0)      w = Wx [k * 512  + g];
    else if (m == 1) w = Wbc[k * 1024 + g];
    else if (m == 2) w = Wbc[k * 1024 + 512 + g];
    else             w = Wd [k * 512  + g];
    __nv_bfloat16 hi = __float2bfloat16(w);
    float lo = w - __bfloat162float(hi);
    g_Wp1[(size_t)k * 2048 + j] = hi;
    // fp8 corr operand: q<128 rows hold Wl*2^14 byte-pairs, q>=128 hold Wh*2^4
    g_Wp8[(size_t)(k >> 1) * 4096 + j * 2 + (k & 1)]         = f8e4(lo * 16384.0f);
    g_Wp8[(size_t)(128 + (k >> 1)) * 4096 + j * 2 + (k & 1)] = f8e4(w * 16.0f);
}

__global__ void pack_wy_kernel(const float* __restrict__ Wy) {
    int idx = blockIdx.x * 256 + threadIdx.x;            // 512*256 total
    int k = idx >> 8, j = idx & 255;
    float w = Wy[k * 256 + j];
    __nv_bfloat16 hi = __float2bfloat16(w);
    float lo = w - __bfloat162float(hi);
    g_Wyp[(size_t)k * 256 + j] = hi;
    g_Wy8[(size_t)(k >> 1) * 512 + j * 2 + (k & 1)]         = f8e4(lo * 16384.0f);
    g_Wy8[(size_t)(256 + (k >> 1)) * 512 + j * 2 + (k & 1)] = f8e4(w * 16.0f);
}

// ------------------------------ GEMM (mma.sync) -----------------------------
// Byte-addressed tiles: A 128 rows x 64B (+16B pad = 80B stride), B 32 k-rows
// x 256B (+16B pad = 272B stride). fp8 phase first (kt < HALF), then acc is
// scaled by 2^-14 and the bf16 main phase accumulates on top.
#define STAGES 4
constexpr int A_STB = 128 * 80;                // 10240 B per stage
constexpr int B_STB = 32 * 272;                // 8704 B per stage
constexpr int SM_BYTES = STAGES * (A_STB + B_STB);        // 75776
constexpr int GEMM_SMEM = SM_BYTES + 256;                 // + reduce buffer

// MODE 1: gemm1 (KT=16, HALF=8,  Astride=512B,  Bstride=4096B, fused epilogue)
// MODE 2: gemm2 (KT=32, HALF=16, Astride=1024B, Bstride=512B,  bias -> out)
template <int MODE>
__global__ void __launch_bounds__(256, 2)
gemm_fused(const uint8_t* __restrict__ A8, const __nv_bfloat16* __restrict__ AH,
           const uint8_t* __restrict__ B8, const __nv_bfloat16* __restrict__ BH,
           const float* __restrict__ bias,
           const float* __restrict__ bx, const float* __restrict__ bbc,
           const float* __restrict__ bd,
           float* __restrict__ Cout_) {
    extern __shared__ __align__(16) char smc[];
    char* As = smc;
    char* Bs = smc + STAGES * A_STB;

    constexpr int KT   = (MODE == 1) ? 16 : 32;
    constexpr int HALF = KT / 2;
    constexpr int ASTR = (MODE == 1) ? 512 : 1024;   // A row stride bytes
    constexpr int BSTR = (MODE == 1) ? 4096 : 512;   // B row stride bytes

    const int tid = threadIdx.x, lane = tid & 31, warp = tid >> 5;
    const int wm = (warp >> 2) * 64, wn = (warp & 3) * 32;
    const int bm = blockIdx.y * 128, bn = blockIdx.x * 128;

    float acc[4][4][4];
#pragma unroll
    for (int i = 0; i < 4; i++)
#pragma unroll
        for (int j = 0; j < 4; j++)
#pragma unroll
            for (int q = 0; q < 4; q++) acc[i][j][q] = 0.f;

    auto load_tile = [&](int kt, int st) {
        const char* Ab;
        const char* Bb;
        if (kt < HALF) {
            Ab = (const char*)A8 + kt * 64;
            Bb = (const char*)B8 + (size_t)(kt * 32) * BSTR;
        } else {
            Ab = (const char*)AH + (kt - HALF) * 64;
            Bb = (const char*)BH + (size_t)((kt - HALF) * 32) * BSTR;
        }
        char* as = As + st * A_STB;
#pragma unroll
        for (int i = 0; i < 2; i++) {                // A: 128 rows x 4 x16B
            int c = tid + i * 256;
            int row = c >> 2, sg = c & 3;
            asm volatile("cp.async.cg.shared.global [%0], [%1], 16;" ::
                         "r"(smem_u32(as + row * 80 + sg * 16)),
                         "l"(Ab + (size_t)row * ASTR + (size_t)bm * ASTR + sg * 16));
        }
        char* bs = Bs + st * B_STB;
#pragma unroll
        for (int i = 0; i < 2; i++) {                // B: 32 rows x 16 x16B
            int c = tid + i * 256;
            int row = c >> 4, sg = c & 15;
            asm volatile("cp.async.cg.shared.global [%0], [%1], 16;" ::
                         "r"(smem_u32(bs + row * 272 + sg * 16)),
                         "l"(Bb + (size_t)row * BSTR + bn * 2 + sg * 16));
        }
        asm volatile("cp.async.commit_group;");
    };

    load_tile(0, 0);
    load_tile(1, 1);
    load_tile(2, 2);

#pragma unroll 1
    for (int kt = 0; kt < KT; kt++) {
        int s = kt & 3;
        if (kt + 2 < KT)      asm volatile("cp.async.wait_group 2;");
        else if (kt + 1 < KT) asm volatile("cp.async.wait_group 1;");
        else                  asm volatile("cp.async.wait_group 0;");
        __syncthreads();
        if (kt + 3 < KT) load_tile(kt + 3, (kt + 3) & 3);

        char* as = As + s * A_STB;
        char* bs = Bs + s * B_STB;
#pragma unroll
        for (int ks = 0; ks < 2; ks++) {
            uint32_t af[4][4];
            uint32_t bf[4][2];
#pragma unroll
            for (int mf = 0; mf < 4; mf++) {
                uint32_t addr = smem_u32(
                    as + (wm + mf * 16 + (lane & 15)) * 80 + ks * 32 + (lane >> 4) * 16);
                asm volatile(
                    "ldmatrix.sync.aligned.m8n8.x4.shared.b16 {%0,%1,%2,%3}, [%4];\n"
                    : "=r"(af[mf][0]), "=r"(af[mf][1]), "=r"(af[mf][2]), "=r"(af[mf][3])
                    : "r"(addr));
            }
#pragma unroll
            for (int p = 0; p < 2; p++) {
                uint32_t addr = smem_u32(
                    bs + (ks * 16 + (lane & 15)) * 272 + (wn + p * 16 + (lane >> 4) * 8) * 2);
                uint32_t r0, r1, r2, r3;
                asm volatile(
                    "ldmatrix.sync.aligned.m8n8.x4.trans.shared.b16 {%0,%1,%2,%3}, [%4];\n"
                    : "=r"(r0), "=r"(r1), "=r"(r2), "=r"(r3)
                    : "r"(addr));
                bf[p * 2][0] = r0;     bf[p * 2][1] = r1;
                bf[p * 2 + 1][0] = r2; bf[p * 2 + 1][1] = r3;
            }
            if (kt < HALF) {
#pragma unroll
                for (int mf = 0; mf < 4; mf++) {
#pragma unroll
                    for (int nf = 0; nf < 4; nf++) {
                        asm volatile(
                            "mma.sync.aligned.m16n8k32.row.col.f32.e4m3.e4m3.f32 "
                            "{%0,%1,%2,%3}, {%4,%5,%6,%7}, {%8,%9}, {%0,%1,%2,%3};\n"
                            : "+f"(acc[mf][nf][0]), "+f"(acc[mf][nf][1]),
                              "+f"(acc[mf][nf][2]), "+f"(acc[mf][nf][3])
                            : "r"(af[mf][0]), "r"(af[mf][1]), "r"(af[mf][2]), "r"(af[mf][3]),
                              "r"(bf[nf][0]), "r"(bf[nf][1]));
                    }
                }
            } else {
#pragma unroll
                for (int mf = 0; mf < 4; mf++) {
#pragma unroll
                    for (int nf = 0; nf < 4; nf++) {
                        asm volatile(
                            "mma.sync.aligned.m16n8k16.row.col.f32.bf16.bf16.f32 "
                            "{%0,%1,%2,%3}, {%4,%5,%6,%7}, {%8,%9}, {%0,%1,%2,%3};\n"
                            : "+f"(acc[mf][nf][0]), "+f"(acc[mf][nf][1]),
                              "+f"(acc[mf][nf][2]), "+f"(acc[mf][nf][3])
                            : "r"(af[mf][0]), "r"(af[mf][1]), "r"(af[mf][2]), "r"(af[mf][3]),
                              "r"(bf[nf][0]), "r"(bf[nf][1]));
                    }
                }
            }
        }
        if (kt == HALF - 1) {
            constexpr float S = 1.0f / 16384.0f;     // undo 2^14 operand scales
#pragma unroll
            for (int i = 0; i < 4; i++)
#pragma unroll
                for (int j = 0; j < 4; j++)
#pragma unroll
                    for (int q = 0; q < 4; q++) acc[i][j][q] *= S;
        }
    }

    if (MODE == 2) {
#pragma unroll
        for (int mf = 0; mf < 4; mf++) {
#pragma unroll
            for (int nf = 0; nf < 4; nf++) {
                int row = bm + wm + mf * 16 + (lane >> 2);
                int col = bn + wn + nf * 8 + (lane & 3) * 2;
                float b0 = bias[col], b1 = bias[col + 1];
                *reinterpret_cast<float2*>(Cout_ + (size_t)row * kCout + col) =
                    make_float2(acc[mf][nf][0] + b0, acc[mf][nf][1] + b1);
                *reinterpret_cast<float2*>(Cout_ + (size_t)(row + 8) * kCout + col) =
                    make_float2(acc[mf][nf][2] + b0, acc[mf][nf][3] + b1);
            }
        }
    } else {
        // Fused S6 elementwise + per-chunk scan aggregates (CTA rows = chunk).
        float2* buf2 = reinterpret_cast<float2*>(smc + SM_BYTES);  // 32 float2
        const int gbase = (bn >> 2) + (wn >> 2) + (lane & 3);
        float Akeep[2], Bkeep[2];
#pragma unroll
        for (int t2 = 0; t2 < 2; t2++) {
            int g = gbase + t2 * 4;
            float vbx = bx[g], vbb = bbc[g], vbc = bbc[512 + g], vbd = bd[g];
            float At = 1.f, Bt = 0.f;
#pragma unroll
            for (int mf = 0; mf < 4; mf++) {
#pragma unroll
                for (int h = 0; h < 2; h++) {
                    int R = bm + wm + mf * 16 + h * 8 + (lane >> 2);
                    float xv = acc[mf][2 * t2 + 0][h * 2 + 0] + vbx;
                    float bv = acc[mf][2 * t2 + 0][h * 2 + 1] + vbb;
                    float cc = acc[mf][2 * t2 + 1][h * 2 + 0] + vbc;
                    float dd = acc[mf][2 * t2 + 1][h * 2 + 1] + vbd;
                    float Aa = 1.0f / (1.0f + expf(dd));
                    float uu = (1.0f - Aa) * bv * xv;
                    size_t o = (size_t)R * kN + g;
                    g_a[o] = Aa;
                    g_u[o] = uu;
                    g_c[o] = cc;
                    float A1 = Aa, B1 = uu;
#pragma unroll
                    for (int st = 4; st <= 16; st <<= 1) {
                        float pa = __shfl_xor_sync(0xffffffffu, A1, st);
                        float pb = __shfl_xor_sync(0xffffffffu, B1, st);
                        if ((lane & st) == 0) {
                            B1 = pa * B1 + pb;
                            A1 = A1 * pa;
                        } else {
                            B1 = A1 * pb + B1;
                            A1 = pa * A1;
                        }
                    }
                    Bt = A1 * Bt + B1;
                    At = At * A1;
                }
            }
            Akeep[t2] = At;
            Bkeep[t2] = Bt;
            if (warp < 4 && (lane >> 2) == 0) {
                int lg = (warp & 3) * 8 + (lane & 3) + t2 * 4;
                buf2[lg] = make_float2(At, Bt);
            }
        }
        __syncthreads();
        if (warp >= 4 && (lane >> 2) == 0) {
#pragma unroll
            for (int t2 = 0; t2 < 2; t2++) {
                int lg = (warp & 3) * 8 + (lane & 3) + t2 * 4;
                float2 lo = buf2[lg];
                int g = gbase + t2 * 4;
                float Ac = lo.x * Akeep[t2];
                float Bc = Akeep[t2] * lo.y + Bkeep[t2];
                int ci = blockIdx.y * kN + g;
                g_Ag[ci] = Ac;
                g_Bg[ci] = Bc;
            }
        }
    }
}

// ------------------------------- chunked scan -------------------------------
__global__ void scan_phase2() {                   // exclusive prefix over chunks
    int n = threadIdx.x, b = blockIdx.x;
    float h = 0.f;
    for (int ch = 0; ch < kNCH; ch++) {
        int idx = (b * kNCH + ch) * kN + n;
        g_H[idx] = h;
        h = fmaf(g_Ag[idx], h, g_Bg[idx]);
    }
}

__global__ void scan_phase3() {                   // final scan, emit packed y
    int n = threadIdx.x, ch = blockIdx.x, b = blockIdx.y;
    int idx = (b * kNCH + ch) * kN + n;
    float h = g_H[idx];
    int row0 = b * kL + ch * kCH;
    size_t base = (size_t)row0 * kN + n;
#pragma unroll 4
    for (int t = 0; t < kCH; t++) {
        size_t o = base + (size_t)t * kN;
        float a = g_a[o], u = g_u[o], c = g_c[o];
        h = fmaf(a, h, u);
        float y = c * h;
        __nv_bfloat16 hi = __float2bfloat16(y);
        float lo = y - __bfloat162float(hi);
        size_t r = (size_t)(row0 + t);
        g_y1p[r * 512 + n]      = hi;
        g_y8 [r * 1024 + n]       = f8e4(y);
        g_y8 [r * 1024 + 512 + n] = f8e4(lo * 1024.0f);
    }
}

// --------------------------------- launcher ---------------------------------
extern "C" void kernel_launch(void* const* d_in, const int* in_sizes, int n_in,
                              void* d_out, int out_size) {
    const float* x   = (const float*)d_in[0];
    const float* Wx  = (const float*)d_in[1];
    const float* bx  = (const float*)d_in[2];
    const float* Wbc = (const float*)d_in[3];
    const float* bbc = (const float*)d_in[4];
    const float* Wd  = (const float*)d_in[5];
    const float* bd  = (const float*)d_in[6];
    const float* Wy  = (const float*)d_in[7];
    const float* by  = (const float*)d_in[8];
    float* out = (float*)d_out;
    (void)in_sizes; (void)n_in; (void)out_size;

    void *p_xp, *p_xp8, *p_wp1, *p_wp8, *p_y1p, *p_y8, *p_wyp, *p_wy8;
    cudaGetSymbolAddress(&p_xp,  g_xp);
    cudaGetSymbolAddress(&p_xp8, g_xp8);
    cudaGetSymbolAddress(&p_wp1, g_Wp1);
    cudaGetSymbolAddress(&p_wp8, g_Wp8);
    cudaGetSymbolAddress(&p_y1p, g_y1p);
    cudaGetSymbolAddress(&p_y8,  g_y8);
    cudaGetSymbolAddress(&p_wyp, g_Wyp);
    cudaGetSymbolAddress(&p_wy8, g_Wy8);

    cudaFuncSetAttribute(gemm_fused<1>, cudaFuncAttributeMaxDynamicSharedMemorySize, GEMM_SMEM);
    cudaFuncSetAttribute(gemm_fused<2>, cudaFuncAttributeMaxDynamicSharedMemorySize, GEMM_SMEM);

    pack_x_kernel <<<(kBL * 64) / 256, 256>>>(x);
    pack_w1_kernel<<<(256 * 2048) / 256, 256>>>(Wx, Wbc, Wd);
    pack_wy_kernel<<<(512 * 256) / 256, 256>>>(Wy);

    gemm_fused<1><<<dim3(16, 128), 256, GEMM_SMEM>>>(
        (const uint8_t*)p_xp8, (const __nv_bfloat16*)p_xp,
        (const uint8_t*)p_wp8, (const __nv_bfloat16*)p_wp1,
        nullptr, bx, bbc, bd, nullptr);

    scan_phase2<<<kB, kN>>>();
    scan_phase3<<<dim3(kNCH, kB), kN>>>();

    gemm_fused<2><<<dim3(2, 128), 256, GEMM_SMEM>>>(
        (const uint8_t*)p_y8, (const __nv_bfloat16*)p_y1p,
        (const uint8_t*)p_wy8, (const __nv_bfloat16*)p_wyp,
        by, nullptr, nullptr, nullptr, out);
}

// round 8
// speedup vs baseline: 1.3234x; 1.1712x over previous
#include <cuda_runtime.h>
#include <cuda_bf16.h>
#include <cuda_fp8.h>
#include <cstdint>

// ---------------------------------------------------------------------------
// S6 block, legacy mma.sync path (tcgen05 unavailable on this build).
// gemm1: bf16 main + fp8 corr (same tensor cycles, less traffic), fused S6
//        elementwise + per-64-row-chunk scan aggregates in the epilogue.
// scan2: tiny chunk-prefix with prefetch ring.
// gemm2f: per-chunk CTA runs the 64-step scan in its prologue, materializes
//        the [yh|yl] bf16 operand in resident smem, then does the output GEMM
//        (3-term bf16, dedup hi) with B streamed via cp.async. y never hits
//        DRAM. Shapes fixed: B=4, L=4096, Cin=256, N=512, Cout=256.
// ---------------------------------------------------------------------------

constexpr int kBL = 16384, kN = 512, kCout = 256, kL = 4096, kB = 4;
constexpr int kNCH = 64, kCH = 64;               // 64-row chunks, 256 total

// ------------------------- scratch (device globals) ------------------------
__device__ __nv_bfloat16 g_xp [(size_t)kBL * 256];   // xh, [row][256]
__device__ uint8_t       g_xp8[(size_t)kBL * 512];   // [row][ f8(x) | f8(xl*2^10) ]
__device__ __nv_bfloat16 g_Wp1[(size_t)256 * 2048];  // wh, [k][jperm]
__device__ uint8_t       g_Wp8[(size_t)256 * 4096];  // fp8 W pairs (see pack_w1)
__device__ __nv_bfloat16 g_Wyp[(size_t)1024 * 256];  // [ Wyh(512) | Wyl(512) ][ j ]
__device__ float2 g_au[(size_t)kBL * kN];            // (a, u) per element
__device__ float  g_c [(size_t)kBL * kN];
__device__ float2 g_AB[256 * kN];                    // per-chunk (A~, B~)
__device__ float  g_H [256 * kN];                    // chunk-start h

__device__ __forceinline__ uint32_t smem_u32(const void* p) {
    return (uint32_t)__cvta_generic_to_shared(p);
}
__device__ __forceinline__ uint8_t f8e4(float v) {
    return (uint8_t)__nv_cvt_float_to_fp8(v, __NV_SATFINITE, __NV_E4M3);
}

// ------------------------------ pack kernels --------------------------------
__global__ void pack_x_kernel(const float* __restrict__ x) {
    int idx = blockIdx.x * 256 + threadIdx.x;            // kBL*64 total
    int row = idx >> 6, k4 = (idx & 63) << 2;
    float4 v = *(const float4*)(x + (size_t)row * 256 + k4);
    float vv[4] = {v.x, v.y, v.z, v.w};
    __nv_bfloat16 hb[4];
    uint8_t hx[4], lx[4];
#pragma unroll
    for (int i = 0; i < 4; i++) {
        hb[i] = __float2bfloat16(vv[i]);
        float lo = vv[i] - __bfloat162float(hb[i]);
        hx[i] = f8e4(vv[i]);
        lx[i] = f8e4(lo * 1024.0f);
    }
    *(uint64_t*)(g_xp + (size_t)row * 256 + k4) = *(uint64_t*)hb;
    *(uint32_t*)(g_xp8 + (size_t)row * 512 + k4) = *(uint32_t*)hx;
    *(uint32_t*)(g_xp8 + (size_t)row * 512 + 256 + k4) = *(uint32_t*)lx;
}

// Permuted W1 columns. For j = n128*128 + w*32 + nf*8 + q2*2 + r:
//   group g = n128*32 + w*8 + (nf>>1)*4 + q2,  member m = (nf&1)*2 + r
//   m: 0=Wx[:,g] 1=Wbc[:,g] 2=Wbc[:,512+g] 3=Wd[:,g]
__global__ void pack_w1_kernel(const float* __restrict__ Wx,
                               const float* __restrict__ Wbc,
                               const float* __restrict__ Wd) {
    int idx = blockIdx.x * 256 + threadIdx.x;            // 256*2048 total
    int k = idx >> 11, j = idx & 2047;
    int g = (j >> 7) * 32 + ((j >> 5) & 3) * 8 + ((j >> 4) & 1) * 4 + ((j >> 1) & 3);
    int m = ((j >> 3) & 1) * 2 + (j & 1);
    float w;
    if (m == 0)      w = Wx [k * 512  + g];
    else if (m == 1) w = Wbc[k * 1024 + g];
    else if (m == 2) w = Wbc[k * 1024 + 512 + g];
    else             w = Wd [k * 512  + g];
    __nv_bfloat16 hi = __float2bfloat16(w);
    float lo = w - __bfloat162float(hi);
    g_Wp1[(size_t)k * 2048 + j] = hi;
    g_Wp8[(size_t)(k >> 1) * 4096 + j * 2 + (k & 1)]         = f8e4(lo * 16384.0f);
    g_Wp8[(size_t)(128 + (k >> 1)) * 4096 + j * 2 + (k & 1)] = f8e4(w * 16.0f);
}

__global__ void pack_wy_kernel(const float* __restrict__ Wy) {
    int idx = blockIdx.x * 256 + threadIdx.x;            // 1024*256 total
    int kk = idx >> 8, j = idx & 255;
    int seg = kk >> 9, k = kk & 511;
    float w = Wy[k * 256 + j];
    __nv_bfloat16 hi = __float2bfloat16(w);
    __nv_bfloat16 o  = hi;
    if (seg == 1) o = __float2bfloat16(w - __bfloat162float(hi));
    g_Wyp[(size_t)kk * 256 + j] = o;
}

// ------------------------- gemm1 (bf16 + fp8 corr) --------------------------
// Byte-addressed tiles: A 128 rows x 64B (+16B pad = 80B), B 32 k-rows x 256B
// (+16B pad = 272B). fp8 phase (kt<8) then acc *= 2^-14, bf16 phase on top.
#define STAGES 4
constexpr int A_STB = 128 * 80;
constexpr int B_STB = 32 * 272;
constexpr int GEMM1_SMEM = STAGES * (A_STB + B_STB);      // 75776

__global__ void __launch_bounds__(256, 2)
gemm1_fused(const uint8_t* __restrict__ A8, const __nv_bfloat16* __restrict__ AH,
            const uint8_t* __restrict__ B8, const __nv_bfloat16* __restrict__ BH,
            const float* __restrict__ bx, const float* __restrict__ bbc,
            const float* __restrict__ bd) {
    extern __shared__ __align__(16) char smc[];
    char* As = smc;
    char* Bs = smc + STAGES * A_STB;

    constexpr int KT = 16, HALF = 8;
    constexpr int ASTR = 512, BSTR = 4096;

    const int tid = threadIdx.x, lane = tid & 31, warp = tid >> 5;
    const int wm = (warp >> 2) * 64, wn = (warp & 3) * 32;
    const int bm = blockIdx.y * 128, bn = blockIdx.x * 128;

    float acc[4][4][4];
#pragma unroll
    for (int i = 0; i < 4; i++)
#pragma unroll
        for (int j = 0; j < 4; j++)
#pragma unroll
            for (int q = 0; q < 4; q++) acc[i][j][q] = 0.f;

    auto load_tile = [&](int kt, int st) {
        const char* Ab;
        const char* Bb;
        if (kt < HALF) {
            Ab = (const char*)A8 + kt * 64;
            Bb = (const char*)B8 + (size_t)(kt * 32) * BSTR;
        } else {
            Ab = (const char*)AH + (kt - HALF) * 64;
            Bb = (const char*)BH + (size_t)((kt - HALF) * 32) * BSTR;
        }
        char* as = As + st * A_STB;
#pragma unroll
        for (int i = 0; i < 2; i++) {
            int c = tid + i * 256;
            int row = c >> 2, sg = c & 3;
            asm volatile("cp.async.cg.shared.global [%0], [%1], 16;" ::
                         "r"(smem_u32(as + row * 80 + sg * 16)),
                         "l"(Ab + (size_t)(bm + row) * ASTR + sg * 16));
        }
        char* bs = Bs + st * B_STB;
#pragma unroll
        for (int i = 0; i < 2; i++) {
            int c = tid + i * 256;
            int row = c >> 4, sg = c & 15;
            asm volatile("cp.async.cg.shared.global [%0], [%1], 16;" ::
                         "r"(smem_u32(bs + row * 272 + sg * 16)),
                         "l"(Bb + (size_t)row * BSTR + bn * 2 + sg * 16));
        }
        asm volatile("cp.async.commit_group;");
    };

    load_tile(0, 0);
    load_tile(1, 1);
    load_tile(2, 2);

#pragma unroll 1
    for (int kt = 0; kt < KT; kt++) {
        int s = kt & 3;
        if (kt + 2 < KT)      asm volatile("cp.async.wait_group 2;");
        else if (kt + 1 < KT) asm volatile("cp.async.wait_group 1;");
        else                  asm volatile("cp.async.wait_group 0;");
        __syncthreads();
        if (kt + 3 < KT) load_tile(kt + 3, (kt + 3) & 3);

        char* as = As + s * A_STB;
        char* bs = Bs + s * B_STB;
#pragma unroll
        for (int ks = 0; ks < 2; ks++) {
            uint32_t af[4][4];
            uint32_t bf[4][2];
#pragma unroll
            for (int mf = 0; mf < 4; mf++) {
                uint32_t addr = smem_u32(
                    as + (wm + mf * 16 + (lane & 15)) * 80 + ks * 32 + (lane >> 4) * 16);
                asm volatile(
                    "ldmatrix.sync.aligned.m8n8.x4.shared.b16 {%0,%1,%2,%3}, [%4];\n"
                    : "=r"(af[mf][0]), "=r"(af[mf][1]), "=r"(af[mf][2]), "=r"(af[mf][3])
                    : "r"(addr));
            }
#pragma unroll
            for (int p = 0; p < 2; p++) {
                uint32_t addr = smem_u32(
                    bs + (ks * 16 + (lane & 15)) * 272 + (wn + p * 16 + (lane >> 4) * 8) * 2);
                uint32_t r0, r1, r2, r3;
                asm volatile(
                    "ldmatrix.sync.aligned.m8n8.x4.trans.shared.b16 {%0,%1,%2,%3}, [%4];\n"
                    : "=r"(r0), "=r"(r1), "=r"(r2), "=r"(r3)
                    : "r"(addr));
                bf[p * 2][0] = r0;     bf[p * 2][1] = r1;
                bf[p * 2 + 1][0] = r2; bf[p * 2 + 1][1] = r3;
            }
            if (kt < HALF) {
#pragma unroll
                for (int mf = 0; mf < 4; mf++) {
#pragma unroll
                    for (int nf = 0; nf < 4; nf++) {
                        asm volatile(
                            "mma.sync.aligned.m16n8k32.row.col.f32.e4m3.e4m3.f32 "
                            "{%0,%1,%2,%3}, {%4,%5,%6,%7}, {%8,%9}, {%0,%1,%2,%3};\n"
                            : "+f"(acc[mf][nf][0]), "+f"(acc[mf][nf][1]),
                              "+f"(acc[mf][nf][2]), "+f"(acc[mf][nf][3])
                            : "r"(af[mf][0]), "r"(af[mf][1]), "r"(af[mf][2]), "r"(af[mf][3]),
                              "r"(bf[nf][0]), "r"(bf[nf][1]));
                    }
                }
            } else {
#pragma unroll
                for (int mf = 0; mf < 4; mf++) {
#pragma unroll
                    for (int nf = 0; nf < 4; nf++) {
                        asm volatile(
                            "mma.sync.aligned.m16n8k16.row.col.f32.bf16.bf16.f32 "
                            "{%0,%1,%2,%3}, {%4,%5,%6,%7}, {%8,%9}, {%0,%1,%2,%3};\n"
                            : "+f"(acc[mf][nf][0]), "+f"(acc[mf][nf][1]),
                              "+f"(acc[mf][nf][2]), "+f"(acc[mf][nf][3])
                            : "r"(af[mf][0]), "r"(af[mf][1]), "r"(af[mf][2]), "r"(af[mf][3]),
                              "r"(bf[nf][0]), "r"(bf[nf][1]));
                    }
                }
            }
        }
        if (kt == HALF - 1) {
            constexpr float S = 1.0f / 16384.0f;
#pragma unroll
            for (int i = 0; i < 4; i++)
#pragma unroll
                for (int j = 0; j < 4; j++)
#pragma unroll
                    for (int q = 0; q < 4; q++) acc[i][j][q] *= S;
        }
    }

    // Fused S6 elementwise + per-64-row-chunk scan aggregates.
    // Warp-row (warps 0-3 -> rows 0..63, warps 4-7 -> 64..127) == one chunk.
    const int gbase = (bn >> 2) + (wn >> 2) + (lane & 3);
    const int chunk = blockIdx.y * 2 + (warp >> 2);
#pragma unroll
    for (int t2 = 0; t2 < 2; t2++) {
        int g = gbase + t2 * 4;
        float vbx = bx[g], vbb = bbc[g], vbc = bbc[512 + g], vbd = bd[g];
        float At = 1.f, Bt = 0.f;
#pragma unroll
        for (int mf = 0; mf < 4; mf++) {
#pragma unroll
            for (int h = 0; h < 2; h++) {
                int R = bm + wm + mf * 16 + h * 8 + (lane >> 2);
                float xv = acc[mf][2 * t2 + 0][h * 2 + 0] + vbx;
                float bv = acc[mf][2 * t2 + 0][h * 2 + 1] + vbb;
                float cc = acc[mf][2 * t2 + 1][h * 2 + 0] + vbc;
                float dd = acc[mf][2 * t2 + 1][h * 2 + 1] + vbd;
                float Aa = 1.0f / (1.0f + expf(dd));
                float uu = (1.0f - Aa) * bv * xv;
                size_t o = (size_t)R * kN + g;
                g_au[o] = make_float2(Aa, uu);
                g_c[o]  = cc;
                float A1 = Aa, B1 = uu;
#pragma unroll
                for (int st = 4; st <= 16; st <<= 1) {
                    float pa = __shfl_xor_sync(0xffffffffu, A1, st);
                    float pb = __shfl_xor_sync(0xffffffffu, B1, st);
                    if ((lane & st) == 0) {
                        B1 = pa * B1 + pb;
                        A1 = A1 * pa;
                    } else {
                        B1 = A1 * pb + B1;
                        A1 = pa * A1;
                    }
                }
                Bt = A1 * Bt + B1;
                At = At * A1;
            }
        }
        if ((lane >> 2) == 0) g_AB[chunk * kN + g] = make_float2(At, Bt);
    }
}

// ------------------------------- chunk prefix -------------------------------
__global__ void scan_phase2() {
    int b = blockIdx.x >> 1;
    int n = (blockIdx.x & 1) * 256 + threadIdx.x;
    int base = b * 64;
    float2 buf[4];
#pragma unroll
    for (int i = 0; i < 4; i++) buf[i] = g_AB[(base + i) * kN + n];
    float h = 0.f;
#pragma unroll 4
    for (int ch = 0; ch < 64; ch++) {
        float2 cur = buf[ch & 3];
        if (ch + 4 < 64) buf[ch & 3] = g_AB[(base + ch + 4) * kN + n];
        g_H[(base + ch) * kN + n] = h;
        h = fmaf(cur.x, h, cur.y);
    }
}

// ------------------- gemm2f: fused scan + output GEMM -----------------------
// One CTA per 64-row chunk. Prologue: scan 64 steps, write bf16 [yh|yl]
// operand into resident smem. Mainloop: 3-term bf16, A resident, B streamed.
constexpr int AROWE = 1032;                      // 1024 elems + 8 pad
constexpr int A2_BYTES = 64 * AROWE * 2;         // 132096
constexpr int B2ROW = 264;
constexpr int B2_ST = 32 * B2ROW;                // elems per stage
constexpr int GEMM2_SMEM = A2_BYTES + STAGES * B2_ST * 2;   // 199680

__global__ void __launch_bounds__(256, 1)
gemm2f(const __nv_bfloat16* __restrict__ Bw,   // g_Wyp [1024][256]
       const float* __restrict__ bias,
       float* __restrict__ Cout_) {
    extern __shared__ __align__(16) char smc[];
    __nv_bfloat16* As = (__nv_bfloat16*)smc;
    __nv_bfloat16* Bs = (__nv_bfloat16*)(smc + A2_BYTES);

    constexpr int KT = 48, S = 16;
    const int tid = threadIdx.x, lane = tid & 31, warp = tid >> 5;
    const int wn = warp * 32;
    const int chunk = blockIdx.x;
    const int row0 = chunk * 64;

    auto load_B = [&](int kt, int st) {
        int seg = (kt >= 2 * S) ? 2 : ((kt >= S) ? 1 : 0);
        int kk  = kt - seg * S;
        int boff = ((seg == 1) ? 512 : 0) + kk * 32;
        const __nv_bfloat16* Bb = Bw + (size_t)boff * 256;
        __nv_bfloat16* bs = Bs + st * B2_ST;
#pragma unroll
        for (int i = 0; i < 4; i++) {               // 32 rows x 32 chunks of 8
            int c = tid + i * 256;
            int row = c >> 5, sg = c & 31;
            asm volatile("cp.async.cg.shared.global [%0], [%1], 16;" ::
                         "r"(smem_u32(bs + row * B2ROW + sg * 8)),
                         "l"(Bb + (size_t)row * 256 + sg * 8));
        }
        asm volatile("cp.async.commit_group;");
    };

    // issue first B stages, then run the scan while they fly
    load_B(0, 0);
    load_B(1, 1);
    load_B(2, 2);

    {
        int n = tid * 2;
        float2 h2 = *(const float2*)(g_H + chunk * kN + n);
#pragma unroll 4
        for (int t = 0; t < 64; t++) {
            size_t o = (size_t)(row0 + t) * kN + n;
            float4 au = *(const float4*)(g_au + o);       // (a0,u0,a1,u1)
            float2 c2 = *(const float2*)(g_c + o);
            h2.x = fmaf(au.x, h2.x, au.y);
            h2.y = fmaf(au.z, h2.y, au.w);
            float y0 = c2.x * h2.x;
            float y1 = c2.y * h2.y;
            __nv_bfloat16 hb0 = __float2bfloat16(y0);
            __nv_bfloat16 hb1 = __float2bfloat16(y1);
            __nv_bfloat16 lb0 = __float2bfloat16(y0 - __bfloat162float(hb0));
            __nv_bfloat16 lb1 = __float2bfloat16(y1 - __bfloat162float(hb1));
            *(__nv_bfloat162*)(As + t * AROWE + n)       = __halves2bfloat162(hb0, hb1);
            *(__nv_bfloat162*)(As + t * AROWE + 512 + n) = __halves2bfloat162(lb0, lb1);
        }
    }
    __syncthreads();                                // A operand ready

    float acc[4][4][4];
#pragma unroll
    for (int i = 0; i < 4; i++)
#pragma unroll
        for (int j = 0; j < 4; j++)
#pragma unroll
            for (int q = 0; q < 4; q++) acc[i][j][q] = 0.f;

#pragma unroll 1
    for (int kt = 0; kt < KT; kt++) {
        int s = kt & 3;
        if (kt + 2 < KT)      asm volatile("cp.async.wait_group 2;");
        else if (kt + 1 < KT) asm volatile("cp.async.wait_group 1;");
        else                  asm volatile("cp.async.wait_group 0;");
        __syncthreads();
        if (kt + 3 < KT) load_B(kt + 3, (kt + 3) & 3);

        int seg = (kt >= 2 * S) ? 2 : ((kt >= S) ? 1 : 0);
        int aoff = ((seg == 2) ? 512 : 0) + (kt - seg * S) * 32;
        __nv_bfloat16* bs = Bs + s * B2_ST;
#pragma unroll
        for (int ks = 0; ks < 2; ks++) {
            uint32_t af[4][4];
            uint32_t bf[4][2];
#pragma unroll
            for (int mf = 0; mf < 4; mf++) {
                uint32_t addr = smem_u32(
                    As + (mf * 16 + (lane & 15)) * AROWE + aoff + ks * 16 + (lane >> 4) * 8);
                asm volatile(
                    "ldmatrix.sync.aligned.m8n8.x4.shared.b16 {%0,%1,%2,%3}, [%4];\n"
                    : "=r"(af[mf][0]), "=r"(af[mf][1]), "=r"(af[mf][2]), "=r"(af[mf][3])
                    : "r"(addr));
            }
#pragma unroll
            for (int p = 0; p < 2; p++) {
                uint32_t addr = smem_u32(
                    bs + (ks * 16 + (lane & 15)) * B2ROW + wn + p * 16 + (lane >> 4) * 8);
                uint32_t r0, r1, r2, r3;
                asm volatile(
                    "ldmatrix.sync.aligned.m8n8.x4.trans.shared.b16 {%0,%1,%2,%3}, [%4];\n"
                    : "=r"(r0), "=r"(r1), "=r"(r2), "=r"(r3)
                    : "r"(addr));
                bf[p * 2][0] = r0;     bf[p * 2][1] = r1;
                bf[p * 2 + 1][0] = r2; bf[p * 2 + 1][1] = r3;
            }
#pragma unroll
            for (int mf = 0; mf < 4; mf++) {
#pragma unroll
                for (int nf = 0; nf < 4; nf++) {
                    asm volatile(
                        "mma.sync.aligned.m16n8k16.row.col.f32.bf16.bf16.f32 "
                        "{%0,%1,%2,%3}, {%4,%5,%6,%7}, {%8,%9}, {%0,%1,%2,%3};\n"
                        : "+f"(acc[mf][nf][0]), "+f"(acc[mf][nf][1]),
                          "+f"(acc[mf][nf][2]), "+f"(acc[mf][nf][3])
                        : "r"(af[mf][0]), "r"(af[mf][1]), "r"(af[mf][2]), "r"(af[mf][3]),
                          "r"(bf[nf][0]), "r"(bf[nf][1]));
                }
            }
        }
    }

#pragma unroll
    for (int mf = 0; mf < 4; mf++) {
#pragma unroll
        for (int nf = 0; nf < 4; nf++) {
            int row = row0 + mf * 16 + (lane >> 2);
            int col = wn + nf * 8 + (lane & 3) * 2;
            float b0 = bias[col], b1 = bias[col + 1];
            *reinterpret_cast<float2*>(Cout_ + (size_t)row * kCout + col) =
                make_float2(acc[mf][nf][0] + b0, acc[mf][nf][1] + b1);
            *reinterpret_cast<float2*>(Cout_ + (size_t)(row + 8) * kCout + col) =
                make_float2(acc[mf][nf][2] + b0, acc[mf][nf][3] + b1);
        }
    }
}

// --------------------------------- launcher ---------------------------------
extern "C" void kernel_launch(void* const* d_in, const int* in_sizes, int n_in,
                              void* d_out, int out_size) {
    const float* x   = (const float*)d_in[0];
    const float* Wx  = (const float*)d_in[1];
    const float* bx  = (const float*)d_in[2];
    const float* Wbc = (const float*)d_in[3];
    const float* bbc = (const float*)d_in[4];
    const float* Wd  = (const float*)d_in[5];
    const float* bd  = (const float*)d_in[6];
    const float* Wy  = (const float*)d_in[7];
    const float* by  = (const float*)d_in[8];
    float* out = (float*)d_out;
    (void)in_sizes; (void)n_in; (void)out_size;

    void *p_xp, *p_xp8, *p_wp1, *p_wp8, *p_wyp;
    cudaGetSymbolAddress(&p_xp,  g_xp);
    cudaGetSymbolAddress(&p_xp8, g_xp8);
    cudaGetSymbolAddress(&p_wp1, g_Wp1);
    cudaGetSymbolAddress(&p_wp8, g_Wp8);
    cudaGetSymbolAddress(&p_wyp, g_Wyp);

    cudaFuncSetAttribute(gemm1_fused, cudaFuncAttributeMaxDynamicSharedMemorySize, GEMM1_SMEM);
    cudaFuncSetAttribute(gemm2f,      cudaFuncAttributeMaxDynamicSharedMemorySize, GEMM2_SMEM);

    pack_x_kernel <<<(kBL * 64) / 256, 256>>>(x);
    pack_w1_kernel<<<(256 * 2048) / 256, 256>>>(Wx, Wbc, Wd);
    pack_wy_kernel<<<(1024 * 256) / 256, 256>>>(Wy);

    gemm1_fused<<<dim3(16, 128), 256, GEMM1_SMEM>>>(
        (const uint8_t*)p_xp8, (const __nv_bfloat16*)p_xp,
        (const uint8_t*)p_wp8, (const __nv_bfloat16*)p_wp1,
        bx, bbc, bd);

    scan_phase2<<<8, 256>>>();

    gemm2f<<<256, 256, GEMM2_SMEM>>>(
        (const __nv_bfloat16*)p_wyp, by, out);
}